// round 5
// baseline (speedup 1.0000x reference)
#include <cuda_runtime.h>
#include <math.h>

// Fused ConvTranspose2d(64->64,k4,s2,p1) + BN(inference) + softmax(ch) + maxpool2x2
// x: [32,64,64,64] f32, w: [Cin64,Cout64,4,4], out: [32,64,64,64] f32
//
// R2: packed fp32 math via PTX fma.rn.f32x2 — channel pairs in 64-bit regs,
// halving FFMA instruction count (the R1 kernel sat exactly on the scalar
// FFMA issue roofline).

#define CIN 64
#define COUT 64
#define XS_W 66                      // 64 cols + 2 halo (zero padded)
#define XS_ROW (CIN * XS_W)          // floats per input row slab
#define XS_SIZE (4 * XS_ROW)         // 16896 floats = 67584 B
#define WS_PAD 36                    // per-tap row stride (16B-aligned)
#define WS_CIN_STRIDE (16 * WS_PAD)  // 576 floats per cin
#define WS_SIZE (CIN * WS_CIN_STRIDE) // 36864 floats
#define SMEM_BYTES ((XS_SIZE + WS_SIZE) * 4)  // 215040 B

extern __shared__ float smem[];

// d = a*b + d   (componentwise on packed f32x2 in 64-bit regs)
#define FMA2(d, a, b) \
    asm("fma.rn.f32x2 %0, %1, %2, %3;" : "=l"(d) : "l"(a), "l"(b), "l"(d))

__device__ __forceinline__ unsigned long long pack2(float v) {
    unsigned long long r;
    asm("mov.b64 %0, {%1, %1};" : "=l"(r) : "f"(v));
    return r;
}
__device__ __forceinline__ void unpack2(unsigned long long p, float& lo, float& hi) {
    asm("mov.b64 {%0, %1}, %2;" : "=f"(lo), "=f"(hi) : "l"(p));
}

__global__ __launch_bounds__(256, 1)
void fused_ctbn_softmax_pool(const float* __restrict__ x,
                             const float* __restrict__ w,
                             const float* __restrict__ conv_bias,
                             const float* __restrict__ gamma,
                             const float* __restrict__ beta,
                             const float* __restrict__ rmean,
                             const float* __restrict__ rvar,
                             float* __restrict__ out)
{
    __shared__ float As[COUT];
    __shared__ float Bs[COUT];

    float* xs = smem;            // [4][CIN][XS_W]
    float* ws = smem + XS_SIZE;  // [CIN][16][WS_PAD]  (reused as pool buf later)

    const int t  = threadIdx.x;
    const int pb = blockIdx.x;   // 0..31  (pooled rows 2pb, 2pb+1)
    const int n  = blockIdx.y;   // 0..31

    // Fold BN + conv bias:  y_bn = conv*A + B
    if (t < COUT) {
        float a = gamma[t] * rsqrtf(rvar[t] + 1e-5f);
        As[t] = a;
        Bs[t] = (conv_bias[t] - rmean[t]) * a + beta[t];
    }

    // Load input slab: conv rows 4pb..4pb+3 need input rows ih in [2pb-1, 2pb+2]
    const int ih0 = 2 * pb - 1;
    for (int i = t; i < XS_SIZE; i += 256) {
        int slot = i / XS_ROW;
        int rem  = i - slot * XS_ROW;
        int cin  = rem / XS_W;
        int cs   = rem - cin * XS_W;
        int ih = ih0 + slot;
        int iw = cs - 1;
        float v = 0.f;
        if ((unsigned)ih < 64u && (unsigned)iw < 64u)
            v = x[((n * CIN + cin) * 64 + ih) * 64 + iw];
        xs[i] = v;
    }
    __syncthreads();

    const int rb = t >> 6;
    const int r  = rb >> 1;   // conv-row parity
    const int b  = rb & 1;    // conv-col parity
    const int q  = t & 63;    // pooled column

    // Tap (kh,kw) indices for this parity class
    const int T_hh = (1 - r) * 4 + (1 - b);
    const int T_hl = (1 - r) * 4 + (3 - b);
    const int T_lh = (3 - r) * 4 + (1 - b);
    const int T_ll = (3 - r) * 4 + (3 - b);

    // x row base pointers (lo col at +0, hi col at +1)
    const float* xa0 = xs + (r    ) * XS_ROW + (q + b);
    const float* xb0 = xs + (r + 1) * XS_ROW + (q + b);
    const float* xc0 = xs + (r + 2) * XS_ROW + (q + b);

    float v0[COUT];  // pooled row 2pb,   BN'ed conv outputs per channel
    float v1[COUT];  // pooled row 2pb+1

    #pragma unroll
    for (int ph = 0; ph < 2; ++ph) {
        // Stage weights for cout = ph*32 + [0,32):  ws[cin][tap][co2]
        for (int i = t; i < CIN * 32 * 16; i += 256) {
            int cin = i >> 9;
            int co2 = (i >> 4) & 31;
            int tap = i & 15;
            ws[cin * WS_CIN_STRIDE + tap * WS_PAD + co2] =
                w[(cin * COUT + ph * 32 + co2) * 16 + tap];
        }
        __syncthreads();

        // 16 packed channel-pair accumulators per pooled row
        unsigned long long acc0[16], acc1[16];
        #pragma unroll
        for (int j = 0; j < 16; ++j) { acc0[j] = 0ull; acc1[j] = 0ull; }

        const float* xap = xa0;
        const float* xbp = xb0;
        const float* xcp = xc0;
        const float* wp  = ws;

        for (int cin = 0; cin < CIN; ++cin) {
            unsigned long long xa_lo2 = pack2(xap[0]), xa_hi2 = pack2(xap[1]);
            unsigned long long xb_lo2 = pack2(xbp[0]), xb_hi2 = pack2(xbp[1]);
            unsigned long long xc_lo2 = pack2(xcp[0]), xc_hi2 = pack2(xcp[1]);
            const ulonglong2* whh = (const ulonglong2*)(wp + T_hh * WS_PAD);
            const ulonglong2* whl = (const ulonglong2*)(wp + T_hl * WS_PAD);
            const ulonglong2* wlh = (const ulonglong2*)(wp + T_lh * WS_PAD);
            const ulonglong2* wll = (const ulonglong2*)(wp + T_ll * WS_PAD);
            #pragma unroll
            for (int g = 0; g < 8; ++g) {
                ulonglong2 w0 = whh[g];   // taps for acc0 row-high / acc1 row-high
                ulonglong2 w1 = whl[g];
                ulonglong2 w2 = wlh[g];
                ulonglong2 w3 = wll[g];
                int j0 = 2 * g, j1 = 2 * g + 1;
                FMA2(acc0[j0], xb_hi2, w0.x);
                FMA2(acc0[j0], xb_lo2, w1.x);
                FMA2(acc0[j0], xa_hi2, w2.x);
                FMA2(acc0[j0], xa_lo2, w3.x);
                FMA2(acc1[j0], xc_hi2, w0.x);
                FMA2(acc1[j0], xc_lo2, w1.x);
                FMA2(acc1[j0], xb_hi2, w2.x);
                FMA2(acc1[j0], xb_lo2, w3.x);
                FMA2(acc0[j1], xb_hi2, w0.y);
                FMA2(acc0[j1], xb_lo2, w1.y);
                FMA2(acc0[j1], xa_hi2, w2.y);
                FMA2(acc0[j1], xa_lo2, w3.y);
                FMA2(acc1[j1], xc_hi2, w0.y);
                FMA2(acc1[j1], xc_lo2, w1.y);
                FMA2(acc1[j1], xb_hi2, w2.y);
                FMA2(acc1[j1], xb_lo2, w3.y);
            }
            xap += XS_W; xbp += XS_W; xcp += XS_W;
            wp  += WS_CIN_STRIDE;
        }

        // Unpack + apply folded BN
        #pragma unroll
        for (int j = 0; j < 16; ++j) {
            float a0lo, a0hi, a1lo, a1hi;
            unpack2(acc0[j], a0lo, a0hi);
            unpack2(acc1[j], a1lo, a1hi);
            int co = ph * 32 + 2 * j;
            float Alo = As[co], Blo = Bs[co];
            float Ahi = As[co + 1], Bhi = Bs[co + 1];
            v0[co]     = fmaf(a0lo, Alo, Blo);
            v0[co + 1] = fmaf(a0hi, Ahi, Bhi);
            v1[co]     = fmaf(a1lo, Alo, Blo);
            v1[co + 1] = fmaf(a1hi, Ahi, Bhi);
        }
        __syncthreads();  // ph=0: before ws reload; ph=1: before buf reuse of ws
    }

    // Per-position softmax over 64 channels (register-resident)
    float m0 = v0[0], m1 = v1[0];
    #pragma unroll
    for (int c = 1; c < COUT; ++c) {
        m0 = fmaxf(m0, v0[c]);
        m1 = fmaxf(m1, v1[c]);
    }
    float s0 = 0.f, s1 = 0.f;
    #pragma unroll
    for (int c = 0; c < COUT; ++c) {
        v0[c] = __expf(v0[c] - m0); s0 += v0[c];
        v1[c] = __expf(v1[c] - m1); s1 += v1[c];
    }
    const float inv0 = 1.f / s0;
    const float inv1 = 1.f / s1;

    // Pool buffer over dead ws region: buf[rb][pl][c][q]  (4*2*64*64 floats)
    float* buf = ws;
    #pragma unroll
    for (int c = 0; c < COUT; ++c) {
        buf[((rb * 2 + 0) * COUT + c) * 64 + q] = v0[c] * inv0;
        buf[((rb * 2 + 1) * COUT + c) * 64 + q] = v1[c] * inv1;
    }
    __syncthreads();

    // Max over the 4 parity classes -> pooled output
    const int RB = 2 * COUT * 64;  // 8192
    for (int i = t; i < 2 * COUT * 64; i += 256) {
        int pl = i >> 12;
        int c  = (i >> 6) & 63;
        int qq = i & 63;
        int off = (pl * COUT + c) * 64 + qq;
        float mv = fmaxf(fmaxf(buf[off], buf[off + RB]),
                         fmaxf(buf[off + 2 * RB], buf[off + 3 * RB]));
        out[((n * COUT + c) * 64 + (2 * pb + pl)) * 64 + qq] = mv;
    }
}

extern "C" void kernel_launch(void* const* d_in, const int* in_sizes, int n_in,
                              void* d_out, int out_size)
{
    const float* x         = (const float*)d_in[0];
    const float* w         = (const float*)d_in[1];
    const float* conv_bias = (const float*)d_in[2];
    const float* gamma     = (const float*)d_in[3];
    const float* beta      = (const float*)d_in[4];
    const float* rmean     = (const float*)d_in[5];
    const float* rvar      = (const float*)d_in[6];
    float* out             = (float*)d_out;

    cudaFuncSetAttribute(fused_ctbn_softmax_pool,
                         cudaFuncAttributeMaxDynamicSharedMemorySize, SMEM_BYTES);

    dim3 grid(32, 32);  // (pooled-row pairs, batch)
    fused_ctbn_softmax_pool<<<grid, 256, SMEM_BYTES>>>(
        x, w, conv_bias, gamma, beta, rmean, rvar, out);
}

// round 9
// speedup vs baseline: 1.0944x; 1.0944x over previous
#include <cuda_runtime.h>
#include <mma.h>
#include <math.h>

using namespace nvcuda;

// ConvTranspose2d(64->64,k4,s2,p1)+BN+softmax(ch)+maxpool2x2 via tf32 wmma
// (mma.sync path: works on plain sm_103 target, runs on tensor cores).
//
// Parity decomposition (validated in R1): conv out (oy=2*po+r, ox=2*qo+b),
// taps (dh,dw): ih = po+r+dh-1, iw = qo+b+dw-1, kh = 3-r-2dh, kw = 3-b-2dw.
// Block (pb=pooled row pair, n=batch): per class c=(r,b):
//   C[m=pl*64+q][cout] = sum_{tap,cin} A[m][tap,cin] * W_ct[cin][cout]
// M=128, N=64, K=256; 8 warps, each one 16-row stripe, wmma m16n16k8.

#define CSTR 68                        // padded inner stride (floats)
#define SLAB_F (4 * 66 * CSTR)         // 17952 floats
#define BS_F   (4 * 64 * CSTR)         // 17408 floats
#define C_F    (128 * CSTR)            // 8704 floats
#define OFF_SLAB 0
#define OFF_B  (OFF_SLAB + SLAB_F)
#define OFF_C  (OFF_B + BS_F)
#define OFF_MP (OFF_C + C_F)
#define OFF_AB (OFF_MP + C_F)          // As[64], Bs[64]
#define SMEM_FLOATS (OFF_AB + 128)
#define SMEM_BYTES (SMEM_FLOATS * 4)   // 211,712 B

// Pre-transposed, pre-tf32-rounded weights: [class*4+tap][cin][cout]
__device__ float wT[16 * 4096];

__global__ void prep_weights(const float* __restrict__ w) {
    int idx = blockIdx.x * 256 + threadIdx.x;   // 65536
    int ct  = idx >> 12;
    int e   = idx & 4095;
    int cin = e >> 6, co = e & 63;
    int c = ct >> 2, tp = ct & 3;
    int r = c >> 1, b = c & 1, dh = tp >> 1, dw = tp & 1;
    int kh = 3 - r - 2 * dh;
    int kw = 3 - b - 2 * dw;
    wT[ct * 4096 + cin * 64 + co] =
        wmma::__float_to_tf32(w[(cin * 64 + co) * 16 + kh * 4 + kw]);
}

extern __shared__ float sm[];

__global__ __launch_bounds__(256, 1)
void fused_wmma_kernel(const float* __restrict__ x,
                       const float* __restrict__ conv_bias,
                       const float* __restrict__ gamma,
                       const float* __restrict__ beta,
                       const float* __restrict__ rmean,
                       const float* __restrict__ rvar,
                       float* __restrict__ out)
{
    float* slab = sm + OFF_SLAB;   // [srow 4][col 66][cin CSTR]
    float* Bsm  = sm + OFF_B;      // [tap 4][cin 64][cout CSTR]
    float* Cbuf = sm + OFF_C;      // [m 128][cout CSTR]
    float* Mp   = sm + OFF_MP;     // running max  [m 128][cout CSTR]
    float* As   = sm + OFF_AB;
    float* Bs   = As + 64;

    const int t  = threadIdx.x;
    const int pb = blockIdx.x;     // pooled row pair
    const int n  = blockIdx.y;     // batch

    if (t < 64) {
        float a = gamma[t] * rsqrtf(rvar[t] + 1e-5f);
        As[t] = a;
        Bs[t] = (conv_bias[t] - rmean[t]) * a + beta[t];
    }

    // Input slab (pre-rounded to tf32): rows ih = 2pb-1 .. 2pb+2
    for (int i = t; i < 4 * 64 * 64; i += 256) {
        int iw   = i & 63;
        int cin  = (i >> 6) & 63;
        int srow = i >> 12;
        int ih = 2 * pb - 1 + srow;
        float v = 0.f;
        if ((unsigned)ih < 64u)
            v = x[((n * 64 + cin) * 64 + ih) * 64 + iw];
        slab[(srow * 66 + iw + 1) * CSTR + cin] = wmma::__float_to_tf32(v);
    }
    // halo columns 0 and 65 = 0
    for (int i = t; i < 4 * 2 * 64; i += 256) {
        int cin  = i & 63;
        int side = (i >> 6) & 1;
        int srow = i >> 7;
        slab[(srow * 66 + (side ? 65 : 0)) * CSTR + cin] = 0.f;
    }
    __syncthreads();

    const int w_id = t >> 5;               // warp 0..7
    const int pl   = w_id >> 2;            // m-half
    const int q0   = (w_id & 3) * 16;      // col base within half
    const int m0   = w_id * 16;            // C row base

    for (int c = 0; c < 4; ++c) {
        const int r = c >> 1, b = c & 1;

        // stage class-c B tiles (pre-rounded)
        for (int i = t; i < 4 * 64 * 64; i += 256) {
            int tap = i >> 12;
            int cin = (i >> 6) & 63;
            int co  = i & 63;
            Bsm[(tap * 64 + cin) * CSTR + co] =
                wT[(c * 4 + tap) * 4096 + cin * 64 + co];
        }
        __syncthreads();

        wmma::fragment<wmma::accumulator, 16, 16, 8, float> fc[4];
        #pragma unroll
        for (int nf = 0; nf < 4; ++nf) wmma::fill_fragment(fc[nf], 0.f);

        #pragma unroll
        for (int tap = 0; tap < 4; ++tap) {
            const int dh = tap >> 1, dw = tap & 1;
            const float* abase = slab + ((r + pl + dh) * 66 + q0 + b + dw) * CSTR;
            const float* bbase = Bsm + tap * 64 * CSTR;
            #pragma unroll
            for (int k0 = 0; k0 < 64; k0 += 8) {
                wmma::fragment<wmma::matrix_a, 16, 16, 8,
                               wmma::precision::tf32, wmma::row_major> fa;
                wmma::load_matrix_sync(fa, abase + k0, CSTR);
                #pragma unroll
                for (int nf = 0; nf < 4; ++nf) {
                    wmma::fragment<wmma::matrix_b, 16, 16, 8,
                                   wmma::precision::tf32, wmma::row_major> fb;
                    wmma::load_matrix_sync(fb, bbase + k0 * CSTR + nf * 16, CSTR);
                    wmma::mma_sync(fc[nf], fa, fb, fc[nf]);
                }
            }
        }

        #pragma unroll
        for (int nf = 0; nf < 4; ++nf)
            wmma::store_matrix_sync(Cbuf + m0 * CSTR + nf * 16, fc[nf],
                                    CSTR, wmma::mem_row_major);
        __syncthreads();

        // BN + softmax per conv position, fold into running 2x2 max
        if (t < 128) {
            float v[64];
            const float* crow = Cbuf + t * CSTR;
            #pragma unroll
            for (int j = 0; j < 64; ++j)
                v[j] = fmaf(crow[j], As[j], Bs[j]);
            float m = v[0];
            #pragma unroll
            for (int j = 1; j < 64; ++j) m = fmaxf(m, v[j]);
            float s = 0.f;
            #pragma unroll
            for (int j = 0; j < 64; ++j) { v[j] = __expf(v[j] - m); s += v[j]; }
            const float inv = 1.f / s;

            float* mrow = Mp + t * CSTR;
            if (c == 0) {
                #pragma unroll
                for (int j = 0; j < 64; ++j) mrow[j] = v[j] * inv;
            } else if (c < 3) {
                #pragma unroll
                for (int j = 0; j < 64; ++j) mrow[j] = fmaxf(mrow[j], v[j] * inv);
            } else {
                const int po = 2 * pb + (t >> 6);
                const int q  = t & 63;
                #pragma unroll
                for (int j = 0; j < 64; ++j)
                    out[((n * 64 + j) * 64 + po) * 64 + q] =
                        fmaxf(mrow[j], v[j] * inv);
            }
        }
        __syncthreads();
    }
}

extern "C" void kernel_launch(void* const* d_in, const int* in_sizes, int n_in,
                              void* d_out, int out_size)
{
    const float* x         = (const float*)d_in[0];
    const float* w         = (const float*)d_in[1];
    const float* conv_bias = (const float*)d_in[2];
    const float* gamma     = (const float*)d_in[3];
    const float* beta      = (const float*)d_in[4];
    const float* rmean     = (const float*)d_in[5];
    const float* rvar      = (const float*)d_in[6];
    float* out             = (float*)d_out;

    prep_weights<<<256, 256>>>(w);

    cudaFuncSetAttribute(fused_wmma_kernel,
                         cudaFuncAttributeMaxDynamicSharedMemorySize, SMEM_BYTES);
    dim3 grid(32, 32);
    fused_wmma_kernel<<<grid, 256, SMEM_BYTES>>>(
        x, conv_bias, gamma, beta, rmean, rvar, out);
}